// round 2
// baseline (speedup 1.0000x reference)
#include <cuda_runtime.h>
#include <cuda_bf16.h>

#define SLAB 32768          // 64*512 floats per time slab
#define HS 516              // padded stride (conflict-free LDS.128)

__device__ unsigned int g_cnt[4];

__device__ __forceinline__ void fma2(unsigned long long& d, unsigned long long a, unsigned long long b) {
    asm("fma.rn.f32x2 %0, %1, %2, %0;" : "+l"(d) : "l"(a), "l"(b));
}
__device__ __forceinline__ void add2(unsigned long long& d, unsigned long long a, unsigned long long b) {
    asm("add.rn.f32x2 %0, %1, %2;" : "=l"(d) : "l"(a), "l"(b));
}
__device__ __forceinline__ float2 u2f(unsigned long long v) {
    float2 r; asm("mov.b64 {%0, %1}, %2;" : "=f"(r.x), "=f"(r.y) : "l"(v)); return r;
}

// ---------------- Phase 1: out[t][b][u] = (x @ T)  ----------------
// X:[32768,256] row r=b*512+t ; T:[256,512]. Tile 64m x 32n, BK=16, 128 thr, 4x4/thread, k-packed.
__global__ void __launch_bounds__(128) p1(const float* __restrict__ X,
                                          const float* __restrict__ T,
                                          float* __restrict__ out) {
    __shared__ float As[64 * 20];
    __shared__ float Ts[32 * 20];
    const int tid = threadIdx.x;
    if (blockIdx.x == 0 && blockIdx.y == 0 && tid < 4) g_cnt[tid] = 0u;

    const int rowBase = blockIdx.x * 64;
    const int n0 = blockIdx.y * 32;
    const int mq = tid >> 3;   // 0..15 -> rows mq+16i
    const int nq = tid & 7;    // 0..7  -> cols nq+8j

    unsigned long long acc[4][4];
#pragma unroll
    for (int i = 0; i < 4; ++i)
#pragma unroll
        for (int j = 0; j < 4; ++j) acc[i][j] = 0ull;

    for (int kb = 0; kb < 256; kb += 16) {
#pragma unroll
        for (int i2 = 0; i2 < 2; ++i2) {
            int q = tid + i2 * 128;          // 0..255
            int m = q >> 2, kq = (q & 3) * 4;
            *(float4*)&As[m * 20 + kq] = *(const float4*)&X[(rowBase + m) * 256 + kb + kq];
        }
        {
            int k = tid >> 3, n4 = (tid & 7) * 4;
            float4 v = *(const float4*)&T[(kb + k) * 512 + n0 + n4];
            Ts[(n4 + 0) * 20 + k] = v.x;
            Ts[(n4 + 1) * 20 + k] = v.y;
            Ts[(n4 + 2) * 20 + k] = v.z;
            Ts[(n4 + 3) * 20 + k] = v.w;
        }
        __syncthreads();
#pragma unroll
        for (int k = 0; k < 16; k += 4) {
            ulonglong2 a0 = *(const ulonglong2*)&As[(mq) * 20 + k];
            ulonglong2 a1 = *(const ulonglong2*)&As[(mq + 16) * 20 + k];
            ulonglong2 a2 = *(const ulonglong2*)&As[(mq + 32) * 20 + k];
            ulonglong2 a3 = *(const ulonglong2*)&As[(mq + 48) * 20 + k];
            ulonglong2 b0 = *(const ulonglong2*)&Ts[(nq) * 20 + k];
            ulonglong2 b1 = *(const ulonglong2*)&Ts[(nq + 8) * 20 + k];
            ulonglong2 b2 = *(const ulonglong2*)&Ts[(nq + 16) * 20 + k];
            ulonglong2 b3 = *(const ulonglong2*)&Ts[(nq + 24) * 20 + k];
            fma2(acc[0][0], a0.x, b0.x); fma2(acc[0][0], a0.y, b0.y);
            fma2(acc[0][1], a0.x, b1.x); fma2(acc[0][1], a0.y, b1.y);
            fma2(acc[0][2], a0.x, b2.x); fma2(acc[0][2], a0.y, b2.y);
            fma2(acc[0][3], a0.x, b3.x); fma2(acc[0][3], a0.y, b3.y);
            fma2(acc[1][0], a1.x, b0.x); fma2(acc[1][0], a1.y, b0.y);
            fma2(acc[1][1], a1.x, b1.x); fma2(acc[1][1], a1.y, b1.y);
            fma2(acc[1][2], a1.x, b2.x); fma2(acc[1][2], a1.y, b2.y);
            fma2(acc[1][3], a1.x, b3.x); fma2(acc[1][3], a1.y, b3.y);
            fma2(acc[2][0], a2.x, b0.x); fma2(acc[2][0], a2.y, b0.y);
            fma2(acc[2][1], a2.x, b1.x); fma2(acc[2][1], a2.y, b1.y);
            fma2(acc[2][2], a2.x, b2.x); fma2(acc[2][2], a2.y, b2.y);
            fma2(acc[2][3], a2.x, b3.x); fma2(acc[2][3], a2.y, b3.y);
            fma2(acc[3][0], a3.x, b0.x); fma2(acc[3][0], a3.y, b0.y);
            fma2(acc[3][1], a3.x, b1.x); fma2(acc[3][1], a3.y, b1.y);
            fma2(acc[3][2], a3.x, b2.x); fma2(acc[3][2], a3.y, b2.y);
            fma2(acc[3][3], a3.x, b3.x); fma2(acc[3][3], a3.y, b3.y);
        }
        __syncthreads();
    }
#pragma unroll
    for (int i = 0; i < 4; ++i) {
        int r = rowBase + mq + 16 * i;
        int tt = r & 511, bb = r >> 9;
        float* p = out + tt * SLAB + bb * 512 + n0 + nq;
#pragma unroll
        for (int j = 0; j < 4; ++j) {
            float2 v = u2f(acc[i][j]);
            p[8 * j] = v.x + v.y;
        }
    }
}

// ---------------- Phase 2: recurrence, persistent 128 blocks ----------------
// grid (32,4): blockIdx.x = utile (16 cols), blockIdx.y = batch group (16 rows).
// 256 thr = 8 warps; warp w reduces k-chunk [64w,64w+64). Lane: rows {rq,rq+8}, cols {cq+4j}.
__global__ void __launch_bounds__(256) p2(float* __restrict__ out,
                                          const float* __restrict__ B,
                                          const float* __restrict__ bias,
                                          const float* __restrict__ h0) {
    extern __shared__ float sm[];
    float* Bs = sm;              // 16 x HS
    float* hs = sm + 16 * HS;    // 16 x HS (aliased as red after k-loop)
    unsigned long long* red = (unsigned long long*)hs;  // [8][264]

    const int tid = threadIdx.x;
    const int warp = tid >> 5, lane = tid & 31;
    const int rq = lane & 7, cq = lane >> 3;          // cq 0..3
    const int g = blockIdx.y, n0 = blockIdx.x * 16;
    const int rowBase = g * 16;
    const int kBase = warp * 64;
    const int orow = tid >> 4, ocol = tid & 15;       // reducer's output
    const float bia = bias[n0 + ocol];

    // one-time B slab (transposed): Bs[c][k] = B[k][n0+c]
    for (int idx = tid; idx < 16 * 512; idx += 256) {
        int k = idx >> 4, c = idx & 15;
        Bs[c * HS + k] = B[k * 512 + n0 + c];
    }

    for (int t = 0; t < 512; ++t) {
        if (t == 0) {
            for (int idx = tid; idx < 16 * 512; idx += 256)
                hs[(idx >> 9) * HS + (idx & 511)] = h0[idx & 511];
        } else {
            const float* hsrc = out + (size_t)(t - 1) * SLAB + rowBase * 512;
            for (int idx = tid * 4; idx < 16 * 512; idx += 1024) {
                int r = idx >> 9, k = idx & 511;
                float4 v = __ldcg((const float4*)(hsrc + r * 512 + k));
                *(float4*)&hs[r * HS + k] = v;
            }
        }
        __syncthreads();

        unsigned long long a00 = 0, a01 = 0, a02 = 0, a03 = 0;
        unsigned long long a10 = 0, a11 = 0, a12 = 0, a13 = 0;
        const float* hr0 = hs + rq * HS + kBase;
        const float* hr1 = hs + (rq + 8) * HS + kBase;
        const float* c0 = Bs + cq * HS + kBase;
        const float* c1 = Bs + (cq + 4) * HS + kBase;
        const float* c2 = Bs + (cq + 8) * HS + kBase;
        const float* c3 = Bs + (cq + 12) * HS + kBase;
#pragma unroll
        for (int k = 0; k < 64; k += 4) {
            ulonglong2 h0v = *(const ulonglong2*)(hr0 + k);
            ulonglong2 h1v = *(const ulonglong2*)(hr1 + k);
            ulonglong2 b0 = *(const ulonglong2*)(c0 + k);
            ulonglong2 b1 = *(const ulonglong2*)(c1 + k);
            ulonglong2 b2 = *(const ulonglong2*)(c2 + k);
            ulonglong2 b3 = *(const ulonglong2*)(c3 + k);
            fma2(a00, h0v.x, b0.x); fma2(a00, h0v.y, b0.y);
            fma2(a01, h0v.x, b1.x); fma2(a01, h0v.y, b1.y);
            fma2(a02, h0v.x, b2.x); fma2(a02, h0v.y, b2.y);
            fma2(a03, h0v.x, b3.x); fma2(a03, h0v.y, b3.y);
            fma2(a10, h1v.x, b0.x); fma2(a10, h1v.y, b0.y);
            fma2(a11, h1v.x, b1.x); fma2(a11, h1v.y, b1.y);
            fma2(a12, h1v.x, b2.x); fma2(a12, h1v.y, b2.y);
            fma2(a13, h1v.x, b3.x); fma2(a13, h1v.y, b3.y);
        }
        __syncthreads();  // hs reads done; red may overwrite

        unsigned long long* rw = red + warp * 264;
        rw[(rq) * 16 + cq] = a00;       rw[(rq) * 16 + cq + 4] = a01;
        rw[(rq) * 16 + cq + 8] = a02;   rw[(rq) * 16 + cq + 12] = a03;
        rw[(rq + 8) * 16 + cq] = a10;     rw[(rq + 8) * 16 + cq + 4] = a11;
        rw[(rq + 8) * 16 + cq + 8] = a12; rw[(rq + 8) * 16 + cq + 12] = a13;
        __syncthreads();

        {
            unsigned long long s = red[tid];
#pragma unroll
            for (int w = 1; w < 8; ++w) add2(s, s, red[w * 264 + tid]);
            float2 p = u2f(s);
            float z = p.x + p.y;
            float* op = out + (size_t)t * SLAB + (rowBase + orow) * 512 + n0 + ocol;
            z += *op;                                    // xT from phase 1
            float a = fabsf(z) + bia;
            *op = (a > 0.f) ? copysignf(a, z) : 0.f;     // modrelu
        }
        __threadfence();
        __syncthreads();
        if (tid == 0) {
            atomicAdd(&g_cnt[g], 1u);
            unsigned int tgt = 32u * (t + 1);
            volatile unsigned int* pc = &g_cnt[g];
            while (*pc < tgt) {}
            __threadfence();
        }
        __syncthreads();
    }
}

extern "C" void kernel_launch(void* const* d_in, const int* in_sizes, int n_in,
                              void* d_out, int out_size) {
    const float* x    = (const float*)d_in[0];
    const float* T    = (const float*)d_in[1];
    const float* B    = (const float*)d_in[2];
    const float* bias = (const float*)d_in[3];
    const float* h0   = (const float*)d_in[4];
    float* out = (float*)d_out;

    dim3 g1(512, 16);  // 32768/64 rows x 512/32 cols
    p1<<<g1, 128>>>(x, T, out);

    size_t smem2 = (size_t)(2 * 16 * HS) * sizeof(float);  // 66048 B
    cudaFuncSetAttribute(p2, cudaFuncAttributeMaxDynamicSharedMemorySize, (int)smem2);
    dim3 g2(32, 4);
    p2<<<g2, 256, smem2>>>(out, B, bias, h0);
}